// round 15
// baseline (speedup 1.0000x reference)
#include <cuda_runtime.h>
#include <cuda_fp16.h>
#include <cstdint>

// Problem constants
#define L_LAYERS 2
#define U_DIM    256
#define U4       (U_DIM / 4)
#define U8       (U_DIM / 8)
#define NL_LAB   64
#define B_DIM    128
#define T_DIM    128
#define DEG      5
#define BT       (B_DIM * T_DIM)          // 16384 nodes
#define E_EDGES  (BT * DEG)               // 81920
#define WSZ      (U_DIM * U_DIM)          // 65536 elems per weight matrix

// ---------------------------------------------------------------------------
// Scratch (device globals — no allocation allowed)
// ---------------------------------------------------------------------------
__device__ __half g_Xh[BT * U_DIM];               // fp16 X (GEMM A + gates)
__device__ __half g_Wh[L_LAYERS * 3 * WSZ];       // fp16 W^T, [l][sel][N][K]
__device__ __half g_binh[L_LAYERS * NL_LAB * U_DIM];   // fp16 label biases
__device__ __half g_bouth[L_LAYERS * NL_LAB * U_DIM];
__device__ __half g_XVin[BT * U_DIM];             // fp16 GEMM outputs
__device__ __half g_XVout[BT * U_DIM];
__device__ __half g_XVloop[BT * U_DIM];
__device__ float  g_gin[BT];
__device__ float  g_gout[BT];
__device__ float  g_gloop[BT];
__device__ float  g_enc[B_DIM * U_DIM];

// ---------------------------------------------------------------------------
// helpers
// ---------------------------------------------------------------------------
__device__ __forceinline__ uint2 f4toh4(float4 v) {
    __half2 h01 = __floats2half2_rn(v.x, v.y);
    __half2 h23 = __floats2half2_rn(v.z, v.w);
    uint2 r;
    r.x = *reinterpret_cast<uint32_t*>(&h01);
    r.y = *reinterpret_cast<uint32_t*>(&h23);
    return r;
}

__device__ __forceinline__ void h8tof8(uint4 u, float* f) {
    float2 p;
    p = __half22float2(*reinterpret_cast<__half2*>(&u.x)); f[0] = p.x; f[1] = p.y;
    p = __half22float2(*reinterpret_cast<__half2*>(&u.y)); f[2] = p.x; f[3] = p.y;
    p = __half22float2(*reinterpret_cast<__half2*>(&u.z)); f[4] = p.x; f[5] = p.y;
    p = __half22float2(*reinterpret_cast<__half2*>(&u.w)); f[6] = p.x; f[7] = p.y;
}

__device__ __forceinline__ void mma_f16(float* d, const uint32_t* a,
                                        const uint32_t* b) {
    asm volatile(
        "mma.sync.aligned.m16n8k16.row.col.f32.f16.f16.f32 "
        "{%0,%1,%2,%3}, {%4,%5,%6,%7}, {%8,%9}, {%0,%1,%2,%3};\n"
        : "+f"(d[0]), "+f"(d[1]), "+f"(d[2]), "+f"(d[3])
        : "r"(a[0]), "r"(a[1]), "r"(a[2]), "r"(a[3]), "r"(b[0]), "r"(b[1]));
}

#define LDSM_X4(r0, r1, r2, r3, addr) \
    asm volatile("ldmatrix.sync.aligned.m8n8.x4.shared.b16 {%0,%1,%2,%3}, [%4];" \
                 : "=r"(r0), "=r"(r1), "=r"(r2), "=r"(r3) : "r"(addr))

__device__ __forceinline__ void cp16(void* dst, const void* src) {
    uint32_t d = (uint32_t)__cvta_generic_to_shared(dst);
    asm volatile("cp.async.cg.shared.global [%0], [%1], 16;\n"
                 :: "r"(d), "l"(src));
}
#define CP_COMMIT() asm volatile("cp.async.commit_group;\n" ::: "memory")
#define CP_WAIT1()  asm volatile("cp.async.wait_group 1;\n" ::: "memory")
#define CP_WAIT0()  asm volatile("cp.async.wait_group 0;\n" ::: "memory")

// ---------------------------------------------------------------------------
// 0a) Weight convert + transpose: Wh[l][sel][n][k] = fp16(W[l][sel][k][n])
// ---------------------------------------------------------------------------
__global__ void cvtwT_k(const float* __restrict__ Vin,
                        const float* __restrict__ Vout,
                        const float* __restrict__ Wloop,
                        __half* __restrict__ out)
{
    __shared__ float ts[32][33];
    int z = blockIdx.z;                  // l*3 + sel
    int l = z / 3, sel = z % 3;
    const float* src = ((sel == 0) ? Vin : (sel == 1) ? Vout : Wloop)
                       + (size_t)l * WSZ;
    __half* dst = out + (size_t)z * WSZ;
    int kk = blockIdx.y * 32 + threadIdx.y;
    int nn = blockIdx.x * 32 + threadIdx.x;
    ts[threadIdx.y][threadIdx.x] = src[(size_t)kk * U_DIM + nn];
    __syncthreads();
    int on = blockIdx.x * 32 + threadIdx.y;
    int ok = blockIdx.y * 32 + threadIdx.x;
    dst[(size_t)on * U_DIM + ok] = __float2half_rn(ts[threadIdx.x][threadIdx.y]);
}

// ---------------------------------------------------------------------------
// 0b) Bias convert: fp32 [L*NL*U] -> fp16, both in and out tables.
// ---------------------------------------------------------------------------
__global__ void cvtb_k(const float* __restrict__ b_in,
                       const float* __restrict__ b_out,
                       __half* __restrict__ binh,
                       __half* __restrict__ bouth)
{
    int idx = blockIdx.x * 256 + threadIdx.x;    // float4 index
    float4 v = reinterpret_cast<const float4*>(b_in)[idx];
    reinterpret_cast<uint2*>(binh)[idx] = f4toh4(v);
    v = reinterpret_cast<const float4*>(b_out)[idx];
    reinterpret_cast<uint2*>(bouth)[idx] = f4toh4(v);
}

// ---------------------------------------------------------------------------
// 1) Embedding gather: Xh[n=b*T+t] = fp16(emb[src[t,b]])
// ---------------------------------------------------------------------------
__global__ void embed_k(const int* __restrict__ src,
                        const float* __restrict__ emb,
                        __half* __restrict__ Xh)
{
    int grp = threadIdx.x >> 6;
    int n   = blockIdx.x * 4 + grp;
    int lu  = threadIdx.x & 63;
    int b = n / T_DIM, t = n % T_DIM;
    int tok = src[t * B_DIM + b];
    float4 v = reinterpret_cast<const float4*>(emb)[(size_t)tok * U4 + lu];
    reinterpret_cast<uint2*>(Xh)[(size_t)n * U4 + lu] = f4toh4(v);
}

// ---------------------------------------------------------------------------
// 2) Fused FP16 GEMM + gates. 1D grid of 1152 blocks, 128 threads (4 warps).
//      bid in [0,768): GEMM. 128x128 block tile, 4 warps of 64x64,
//                      BK=32 halves, 3-stage cp.async, ldmatrix x4 (A and
//                      combined B), fp32 accum, fp16 C out.
//      bid in [768,1152): gate GEMVs on fp16 X, grid-stride (384 blocks).
// ---------------------------------------------------------------------------
#define GBM 128
#define GBN 128
#define GBK 32                 // halves per k-tile
#define NT  (U_DIM / GBK)      // 8 k-tiles
#define GTHREADS 128
#define GEMM_BLOCKS 768
#define GATE_BLOCKS 384
#define TOTAL_BLOCKS (GEMM_BLOCKS + GATE_BLOCKS)   // 1152
#define HPITCH 40              // halves per smem row (80B; ldmatrix conflict-free)
#define A_STAGE_H (GBM * HPITCH)     // 5120 halves
#define B_STAGE_H (GBN * HPITCH)     // 5120 halves
#define SMEM_DYN  (3 * (A_STAGE_H + B_STAGE_H) * 2)   // 61,440 B

__global__ __launch_bounds__(GTHREADS, 2)
void gemm_gate_k(const __half* __restrict__ Ah,
                 const __half* __restrict__ Wh,   // [3][N][K] this layer
                 __half* __restrict__ C0, __half* __restrict__ C1,
                 __half* __restrict__ C2,
                 const float* __restrict__ vgin,
                 const float* __restrict__ vgout,
                 const float* __restrict__ wgl,
                 float* __restrict__ gin, float* __restrict__ gout,
                 float* __restrict__ gloop)
{
    const int bid = blockIdx.x;

    // ---------------- gate slice (grid-stride, fp16 X) ----------------
    if (bid >= GEMM_BLOCKS) {
        int gblk = bid - GEMM_BLOCKS;
        int warp = threadIdx.x >> 5;            // 0..3
        int lane = threadIdx.x & 31;
        const float4* v0 = reinterpret_cast<const float4*>(vgin);
        const float4* v1 = reinterpret_cast<const float4*>(vgout);
        const float4* v2 = reinterpret_cast<const float4*>(wgl);
        const int stride = GATE_BLOCKS * 4;     // 1536 warps
#pragma unroll 1
        for (int n = gblk * 4 + warp; n < BT; n += stride) {
            uint4 xu = reinterpret_cast<const uint4*>(
                Ah + (size_t)n * U_DIM)[lane];
            float x[8];
            h8tof8(xu, x);
            float s0 = 0.f, s1 = 0.f, s2 = 0.f;
            int base = lane * 2;    // float4 index into gate vectors
#pragma unroll
            for (int q = 0; q < 2; q++) {
                float4 a = v0[base + q], b = v1[base + q], c = v2[base + q];
                float* xx = x + q * 4;
                s0 += xx[0] * a.x + xx[1] * a.y + xx[2] * a.z + xx[3] * a.w;
                s1 += xx[0] * b.x + xx[1] * b.y + xx[2] * b.z + xx[3] * b.w;
                s2 += xx[0] * c.x + xx[1] * c.y + xx[2] * c.z + xx[3] * c.w;
            }
#pragma unroll
            for (int off = 16; off > 0; off >>= 1) {
                s0 += __shfl_down_sync(0xffffffffu, s0, off);
                s1 += __shfl_down_sync(0xffffffffu, s1, off);
                s2 += __shfl_down_sync(0xffffffffu, s2, off);
            }
            if (lane == 0) { gin[n] = s0; gout[n] = s1; gloop[n] = s2; }
        }
        return;
    }

    // ---------------- GEMM slice ----------------
    const int xb      = bid & 127;
    const int yb      = bid >> 7;              // 0..5
    const int sel     = yb >> 1;
    const int colbase = (yb & 1) * GBN;
    const __half* __restrict__ W = Wh + (size_t)sel * WSZ;   // [N][K]
    __half* __restrict__ C       = (sel == 0) ? C0 : ((sel == 1) ? C1 : C2);
    const int mbase = xb * GBM;

    extern __shared__ __align__(16) __half hsm[];
    __half* Asm = hsm;                         // 3 stages of [GBM][HPITCH]
    __half* Bsm = hsm + 3 * A_STAGE_H;         // 3 stages of [GBN][HPITCH]

    const int tid  = threadIdx.x;
    const int lane = tid & 31;
    const int warp = tid >> 5;                 // 0..3
    const int wm   = (warp & 1) * 64;          // warp M offset
    const int wn   = (warp >> 1) * 64;         // warp N offset
    const int g    = lane >> 2;                // 0..7
    const int t    = lane & 3;                 // 0..3

    // cp.async: 4x 16B per thread per operand per tile
    const int ldRow = tid >> 2;                // 0..31
    const int ldH   = (tid & 3) * 8;           // 0,8,16,24 halves

    const __half* Abase = Ah + (size_t)(mbase + ldRow) * U_DIM + ldH;
    const __half* Wbase = W + (size_t)(colbase + ldRow) * U_DIM + ldH;
    __half* AsmRow = Asm + ldRow * HPITCH + ldH;
    __half* BsmRow = Bsm + ldRow * HPITCH + ldH;

    const uint32_t asmB = (uint32_t)__cvta_generic_to_shared(Asm);
    const uint32_t bsmB = (uint32_t)__cvta_generic_to_shared(Bsm);
    // A x4 fragment base: lane l -> row wm+mi*16+(l&15), k-offset (l>>4)*8
    const uint32_t aOff0 =
        ((wm + (lane & 15)) * HPITCH + ((lane >> 4) << 3)) * 2;
    // B combined x4 (ni pair p): matrices (2p,k0),(2p,k8),(2p+1,k0),(2p+1,k8)
    // lane l -> row wn + (2p + ((l>>4)&1))*8 + (l&7), k-offset ((l>>3)&1)*8
    uint32_t bOff[4];
#pragma unroll
    for (int p = 0; p < 4; p++)
        bOff[p] = ((wn + (2 * p + ((lane >> 4) & 1)) * 8 + (lane & 7)) * HPITCH
                   + (((lane >> 3) & 1) << 3)) * 2;

    float acc[4][8][4];
#pragma unroll
    for (int mi = 0; mi < 4; mi++)
#pragma unroll
        for (int ni = 0; ni < 8; ni++)
#pragma unroll
            for (int c = 0; c < 4; c++) acc[mi][ni][c] = 0.f;

    // prologue: tiles 0 and 1 into stages 0 and 1
#pragma unroll
    for (int j = 0; j < 4; j++) {
        cp16(AsmRow + j * 32 * HPITCH, Abase + (size_t)j * 32 * U_DIM);
        cp16(BsmRow + j * 32 * HPITCH, Wbase + (size_t)j * 32 * U_DIM);
    }
    CP_COMMIT();
#pragma unroll
    for (int j = 0; j < 4; j++) {
        cp16(AsmRow + A_STAGE_H + j * 32 * HPITCH,
             Abase + (size_t)j * 32 * U_DIM + GBK);
        cp16(BsmRow + B_STAGE_H + j * 32 * HPITCH,
             Wbase + (size_t)j * 32 * U_DIM + GBK);
    }
    CP_COMMIT();

#pragma unroll 1
    for (int tile = 0; tile < NT; tile++) {
        if (tile < NT - 1) { CP_WAIT1(); } else { CP_WAIT0(); }
        __syncthreads();   // tile data visible; stage (tile+2)%3 free

        int nxt = tile + 2;
        if (nxt < NT) {
            int s  = nxt % 3;
            int k0 = nxt * GBK;
#pragma unroll
            for (int j = 0; j < 4; j++) {
                cp16(AsmRow + s * A_STAGE_H + j * 32 * HPITCH,
                     Abase + (size_t)j * 32 * U_DIM + k0);
                cp16(BsmRow + s * B_STAGE_H + j * 32 * HPITCH,
                     Wbase + (size_t)j * 32 * U_DIM + k0);
            }
            CP_COMMIT();
        }

        const int st = tile % 3;
        const uint32_t stA = asmB + st * (A_STAGE_H * 2);
        const uint32_t stB = bsmB + st * (B_STAGE_H * 2);
#pragma unroll
        for (int ks = 0; ks < GBK; ks += 16) {
            const uint32_t kByte = ks * 2;
            uint32_t afr[4][4];
#pragma unroll
            for (int mi = 0; mi < 4; mi++)
                LDSM_X4(afr[mi][0], afr[mi][1], afr[mi][2], afr[mi][3],
                        stA + aOff0 + mi * (16 * HPITCH * 2) + kByte);
            uint32_t bfr[8][2];
#pragma unroll
            for (int p = 0; p < 4; p++)
                LDSM_X4(bfr[2 * p][0], bfr[2 * p][1],
                        bfr[2 * p + 1][0], bfr[2 * p + 1][1],
                        stB + bOff[p] + kByte);
#pragma unroll
            for (int mi = 0; mi < 4; mi++)
#pragma unroll
                for (int ni = 0; ni < 8; ni++)
                    mma_f16(acc[mi][ni], afr[mi], bfr[ni]);
        }
    }

    // epilogue: fp16 stores
#pragma unroll
    for (int mi = 0; mi < 4; mi++) {
#pragma unroll
        for (int ni = 0; ni < 8; ni++) {
            int row = mbase + wm + mi * 16 + g;
            int col = colbase + wn + ni * 8 + 2 * t;
            __half2 h0 = __floats2half2_rn(acc[mi][ni][0], acc[mi][ni][1]);
            __half2 h1 = __floats2half2_rn(acc[mi][ni][2], acc[mi][ni][3]);
            *reinterpret_cast<__half2*>(&C[(size_t)row * U_DIM + col])       = h0;
            *reinterpret_cast<__half2*>(&C[(size_t)(row + 8) * U_DIM + col]) = h1;
        }
    }
}

// ---------------------------------------------------------------------------
// 3) Edge aggregation: 32 threads/node, 8 nodes/block; uint4 fp16 gathers,
//    fp16 biases, fp32 accumulation.
// ---------------------------------------------------------------------------
__global__ __launch_bounds__(256)
void agg_k(const __half* __restrict__ XVin,
           const __half* __restrict__ XVout,
           const __half* __restrict__ XVloop,
           const float* __restrict__ gin,
           const float* __restrict__ gout,
           const float* __restrict__ gloop,
           const int* __restrict__ arc_in,
           const int* __restrict__ arc_out,
           const int* __restrict__ lab_in,
           const int* __restrict__ lab_out,
           const __half* __restrict__ binh,
           const float* __restrict__ bg_in,
           const __half* __restrict__ bouth,
           const float* __restrict__ bg_out,
           const float* __restrict__ mask_in,
           const float* __restrict__ mask_out,
           const float* __restrict__ mask_loop,
           const float* __restrict__ sent_mask,
           float* __restrict__ Y, __half* __restrict__ Yh)
{
    int grp = threadIdx.x >> 5;      // node within block (0..7)
    int n   = blockIdx.x * 8 + grp;
    int lu  = threadIdx.x & 31;      // uint4 lane over U

    __shared__ float p_in[8][DEG], p_out[8][DEG], p_loop[8];
    __shared__ int   s_in[8][DEG], s_out[8][DEG], l_in[8][DEG], l_out[8][DEG];

    if (lu < DEG) {
        int d = lu, e = n * DEG + d;
        int si = arc_in[e] * T_DIM + arc_in[E_EDGES + e];
        int li = lab_in[e];
        float gi = gin[si] + bg_in[li];
        p_in[grp][d] = (1.f / (1.f + __expf(-gi))) * mask_in[n * DEG + d];
        s_in[grp][d] = si; l_in[grp][d] = li;
    } else if (lu < 2 * DEG) {
        int d = lu - DEG, e = n * DEG + d;
        int so = arc_out[e] * T_DIM + arc_out[E_EDGES + e];
        int lo = lab_out[e];
        float go = gout[so] + bg_out[lo];
        p_out[grp][d] = (1.f / (1.f + __expf(-go))) * mask_out[n * DEG + d];
        s_out[grp][d] = so; l_out[grp][d] = lo;
    } else if (lu == 2 * DEG) {
        p_loop[grp] = (1.f / (1.f + __expf(-gloop[n]))) * mask_loop[n];
    }
    __syncthreads();

    const uint4* XVin4   = reinterpret_cast<const uint4*>(XVin);
    const uint4* XVout4  = reinterpret_cast<const uint4*>(XVout);
    const uint4* XVloop4 = reinterpret_cast<const uint4*>(XVloop);
    const uint4* bin4    = reinterpret_cast<const uint4*>(binh);
    const uint4* bout4   = reinterpret_cast<const uint4*>(bouth);

    float acc[8], v[8], bb[8];
    {
        float pl = p_loop[grp];
        h8tof8(XVloop4[(size_t)n * U8 + lu], v);
#pragma unroll
        for (int q = 0; q < 8; q++) acc[q] = pl * v[q];
    }

#pragma unroll
    for (int d = 0; d < DEG; d++) {
        float p = p_in[grp][d];
        h8tof8(XVin4[(size_t)s_in[grp][d] * U8 + lu], v);
        h8tof8(bin4[(size_t)l_in[grp][d] * U8 + lu], bb);
#pragma unroll
        for (int q = 0; q < 8; q++)
            acc[q] = fmaf(p, v[q] + bb[q], acc[q]);
        p = p_out[grp][d];
        h8tof8(XVout4[(size_t)s_out[grp][d] * U8 + lu], v);
        h8tof8(bout4[(size_t)l_out[grp][d] * U8 + lu], bb);
#pragma unroll
        for (int q = 0; q < 8; q++)
            acc[q] = fmaf(p, v[q] + bb[q], acc[q]);
    }
    int b = n / T_DIM, t = n % T_DIM;
    float sm = sent_mask[t * B_DIM + b];
#pragma unroll
    for (int q = 0; q < 8; q++)
        acc[q] = fmaxf(acc[q], 0.f) * sm;

    if (Y) {   // fp32 [t,b,u] membank output
        size_t base = ((size_t)t * B_DIM + b) * U4 + lu * 2;
        reinterpret_cast<float4*>(Y)[base] =
            make_float4(acc[0], acc[1], acc[2], acc[3]);
        reinterpret_cast<float4*>(Y)[base + 1] =
            make_float4(acc[4], acc[5], acc[6], acc[7]);
    }
    if (Yh) {  // fp16 node-major (next layer X)
        uint4 u;
        __half2 h;
        h = __floats2half2_rn(acc[0], acc[1]); u.x = *reinterpret_cast<uint32_t*>(&h);
        h = __floats2half2_rn(acc[2], acc[3]); u.y = *reinterpret_cast<uint32_t*>(&h);
        h = __floats2half2_rn(acc[4], acc[5]); u.z = *reinterpret_cast<uint32_t*>(&h);
        h = __floats2half2_rn(acc[6], acc[7]); u.w = *reinterpret_cast<uint32_t*>(&h);
        reinterpret_cast<uint4*>(Yh)[(size_t)n * U8 + lu] = u;
    }
}

// ---------------------------------------------------------------------------
// 4) enc[b] from membank layout
// ---------------------------------------------------------------------------
__global__ void enc_k(const float* __restrict__ MB,
                      const float* __restrict__ sent_mask,
                      float* __restrict__ enc)
{
    int b = blockIdx.x;
    int u = threadIdx.x;  // 0..63
    const float4* M4 = reinterpret_cast<const float4*>(MB);
    float4 s = make_float4(0.f, 0.f, 0.f, 0.f);
#pragma unroll 4
    for (int t = 0; t < T_DIM; t++) {
        float4 v = M4[((size_t)t * B_DIM + b) * U4 + u];
        s.x += v.x; s.y += v.y; s.z += v.z; s.w += v.w;
    }
    __shared__ float ms;
    if (u == 0) {
        float m = 0.f;
        for (int t = 0; t < T_DIM; t++) m += sent_mask[t * B_DIM + b];
        ms = m;
    }
    __syncthreads();
    float inv = 1.f / ms;
    s.x *= inv; s.y *= inv; s.z *= inv; s.w *= inv;
    reinterpret_cast<float4*>(enc)[b * U4 + u] = s;
}

// ---------------------------------------------------------------------------
// 5) h_all[k,b,w] = sum_u enc[b,u] * H[k,u,w]
// ---------------------------------------------------------------------------
__global__ void hall_k(const float* __restrict__ enc,
                       const float* __restrict__ H,
                       float* __restrict__ out)
{
    int k = blockIdx.y, b = blockIdx.x, w = threadIdx.x;
    __shared__ float es[U_DIM];
    es[w] = enc[b * U_DIM + w];
    __syncthreads();
    const float* Hk = H + (size_t)k * U_DIM * U_DIM;
    float acc = 0.f;
#pragma unroll 8
    for (int u = 0; u < U_DIM; u++)
        acc = fmaf(es[u], Hk[u * U_DIM + w], acc);
    out[((size_t)k * B_DIM + b) * U_DIM + w] = acc;
}

// ---------------------------------------------------------------------------
// Launch
// ---------------------------------------------------------------------------
extern "C" void kernel_launch(void* const* d_in, const int* in_sizes, int n_in,
                              void* d_out, int out_size)
{
    const int*   src       = (const int*)  d_in[0];
    const int*   arc_in    = (const int*)  d_in[1];
    const int*   arc_out   = (const int*)  d_in[2];
    const int*   lab_in    = (const int*)  d_in[3];
    const int*   lab_out   = (const int*)  d_in[4];
    const float* mask_in   = (const float*)d_in[5];
    const float* mask_out  = (const float*)d_in[6];
    const float* mask_loop = (const float*)d_in[7];
    const float* sent_mask = (const float*)d_in[8];
    const float* emb       = (const float*)d_in[9];
    const float* V_in      = (const float*)d_in[10];
    const float* b_in      = (const float*)d_in[11];
    const float* Vg_in     = (const float*)d_in[12];
    const float* bg_in     = (const float*)d_in[13];
    const float* V_out     = (const float*)d_in[14];
    const float* b_out     = (const float*)d_in[15];
    const float* Vg_out    = (const float*)d_in[16];
    const float* bg_out    = (const float*)d_in[17];
    const float* W_loop    = (const float*)d_in[18];
    const float* Wg_loop   = (const float*)d_in[19];
    const float* H         = (const float*)d_in[20];
    float* out = (float*)d_out;

    float *pgin, *pgout, *pgloop, *penc;
    __half *pXh, *pWh, *pbinh, *pbouth, *pXVin, *pXVout, *pXVloop;
    cudaGetSymbolAddress((void**)&pXh,     g_Xh);
    cudaGetSymbolAddress((void**)&pWh,     g_Wh);
    cudaGetSymbolAddress((void**)&pbinh,   g_binh);
    cudaGetSymbolAddress((void**)&pbouth,  g_bouth);
    cudaGetSymbolAddress((void**)&pXVin,   g_XVin);
    cudaGetSymbolAddress((void**)&pXVout,  g_XVout);
    cudaGetSymbolAddress((void**)&pXVloop, g_XVloop);
    cudaGetSymbolAddress((void**)&pgin,    g_gin);
    cudaGetSymbolAddress((void**)&pgout,   g_gout);
    cudaGetSymbolAddress((void**)&pgloop,  g_gloop);
    cudaGetSymbolAddress((void**)&penc,    g_enc);

    cudaFuncSetAttribute(gemm_gate_k,
                         cudaFuncAttributeMaxDynamicSharedMemorySize, SMEM_DYN);

    float* memOut = out + 4 * B_DIM * U_DIM;   // membank region of d_out

    cvtwT_k<<<dim3(8, 8, 6), dim3(32, 32)>>>(V_in, V_out, W_loop, pWh);
    cvtb_k<<<L_LAYERS * NL_LAB * U_DIM / 4 / 256, 256>>>(b_in, b_out,
                                                         pbinh, pbouth);
    embed_k<<<BT / 4, 256>>>(src, emb, pXh);

    for (int l = 0; l < L_LAYERS; l++) {
        const size_t gOff  = (size_t)l * U_DIM;
        const size_t bOff  = (size_t)l * NL_LAB * U_DIM;
        const size_t bgOff = (size_t)l * NL_LAB;
        const int last = (l == L_LAYERS - 1);

        gemm_gate_k<<<TOTAL_BLOCKS, GTHREADS, SMEM_DYN>>>(
            pXh, pWh + (size_t)l * 3 * WSZ,
            pXVin, pXVout, pXVloop,
            Vg_in + gOff, Vg_out + gOff, Wg_loop + gOff,
            pgin, pgout, pgloop);
        agg_k<<<BT / 8, 256>>>(pXVin, pXVout, pXVloop, pgin, pgout, pgloop,
                               arc_in, arc_out, lab_in, lab_out,
                               pbinh + bOff, bg_in + bgOff,
                               pbouth + bOff, bg_out + bgOff,
                               mask_in, mask_out, mask_loop, sent_mask,
                               last ? memOut : nullptr,
                               last ? nullptr : pXh);
    }

    enc_k<<<B_DIM, 64>>>(memOut, sent_mask, penc);
    hall_k<<<dim3(B_DIM, 4), U_DIM>>>(penc, H, out);
}

// round 16
// speedup vs baseline: 1.0399x; 1.0399x over previous
#include <cuda_runtime.h>
#include <cuda_fp16.h>
#include <cstdint>

// Problem constants
#define L_LAYERS 2
#define U_DIM    256
#define U4       (U_DIM / 4)
#define U8       (U_DIM / 8)
#define NL_LAB   64
#define B_DIM    128
#define T_DIM    128
#define DEG      5
#define BT       (B_DIM * T_DIM)          // 16384 nodes
#define E_EDGES  (BT * DEG)               // 81920
#define WSZ      (U_DIM * U_DIM)          // 65536 elems per weight matrix

// ---------------------------------------------------------------------------
// Scratch (device globals — no allocation allowed)
// ---------------------------------------------------------------------------
__device__ __half g_Xh[BT * U_DIM];               // fp16 X (GEMM A + gates)
__device__ __half g_Wh[L_LAYERS * 3 * WSZ];       // fp16 W^T, [l][sel][N][K]
__device__ __half g_binh[L_LAYERS * NL_LAB * U_DIM];   // fp16 label biases
__device__ __half g_bouth[L_LAYERS * NL_LAB * U_DIM];
__device__ __half g_XVin[BT * U_DIM];             // fp16 GEMM outputs
__device__ __half g_XVout[BT * U_DIM];
__device__ __half g_XVloop[BT * U_DIM];
__device__ float  g_gin[BT];
__device__ float  g_gout[BT];
__device__ float  g_gloop[BT];
__device__ float  g_enc[B_DIM * U_DIM];

// ---------------------------------------------------------------------------
// helpers
// ---------------------------------------------------------------------------
__device__ __forceinline__ uint2 f4toh4(float4 v) {
    __half2 h01 = __floats2half2_rn(v.x, v.y);
    __half2 h23 = __floats2half2_rn(v.z, v.w);
    uint2 r;
    r.x = *reinterpret_cast<uint32_t*>(&h01);
    r.y = *reinterpret_cast<uint32_t*>(&h23);
    return r;
}

__device__ __forceinline__ void h8tof8(uint4 u, float* f) {
    float2 p;
    p = __half22float2(*reinterpret_cast<__half2*>(&u.x)); f[0] = p.x; f[1] = p.y;
    p = __half22float2(*reinterpret_cast<__half2*>(&u.y)); f[2] = p.x; f[3] = p.y;
    p = __half22float2(*reinterpret_cast<__half2*>(&u.z)); f[4] = p.x; f[5] = p.y;
    p = __half22float2(*reinterpret_cast<__half2*>(&u.w)); f[6] = p.x; f[7] = p.y;
}

__device__ __forceinline__ void mma_f16(float* d, const uint32_t* a,
                                        const uint32_t* b) {
    asm volatile(
        "mma.sync.aligned.m16n8k16.row.col.f32.f16.f16.f32 "
        "{%0,%1,%2,%3}, {%4,%5,%6,%7}, {%8,%9}, {%0,%1,%2,%3};\n"
        : "+f"(d[0]), "+f"(d[1]), "+f"(d[2]), "+f"(d[3])
        : "r"(a[0]), "r"(a[1]), "r"(a[2]), "r"(a[3]), "r"(b[0]), "r"(b[1]));
}

#define LDSM_X4(r0, r1, r2, r3, addr) \
    asm volatile("ldmatrix.sync.aligned.m8n8.x4.shared.b16 {%0,%1,%2,%3}, [%4];" \
                 : "=r"(r0), "=r"(r1), "=r"(r2), "=r"(r3) : "r"(addr))

__device__ __forceinline__ void cp16(void* dst, const void* src) {
    uint32_t d = (uint32_t)__cvta_generic_to_shared(dst);
    asm volatile("cp.async.cg.shared.global [%0], [%1], 16;\n"
                 :: "r"(d), "l"(src));
}
#define CP_COMMIT() asm volatile("cp.async.commit_group;\n" ::: "memory")
#define CP_WAIT1()  asm volatile("cp.async.wait_group 1;\n" ::: "memory")
#define CP_WAIT0()  asm volatile("cp.async.wait_group 0;\n" ::: "memory")

// ---------------------------------------------------------------------------
// 0a) Weight convert + transpose: Wh[l][sel][n][k] = fp16(W[l][sel][k][n])
// ---------------------------------------------------------------------------
__global__ void cvtwT_k(const float* __restrict__ Vin,
                        const float* __restrict__ Vout,
                        const float* __restrict__ Wloop,
                        __half* __restrict__ out)
{
    __shared__ float ts[32][33];
    int z = blockIdx.z;                  // l*3 + sel
    int l = z / 3, sel = z % 3;
    const float* src = ((sel == 0) ? Vin : (sel == 1) ? Vout : Wloop)
                       + (size_t)l * WSZ;
    __half* dst = out + (size_t)z * WSZ;
    int kk = blockIdx.y * 32 + threadIdx.y;
    int nn = blockIdx.x * 32 + threadIdx.x;
    ts[threadIdx.y][threadIdx.x] = src[(size_t)kk * U_DIM + nn];
    __syncthreads();
    int on = blockIdx.x * 32 + threadIdx.y;
    int ok = blockIdx.y * 32 + threadIdx.x;
    dst[(size_t)on * U_DIM + ok] = __float2half_rn(ts[threadIdx.x][threadIdx.y]);
}

// ---------------------------------------------------------------------------
// 0b) Bias convert: fp32 [L*NL*U] -> fp16, both in and out tables.
// ---------------------------------------------------------------------------
__global__ void cvtb_k(const float* __restrict__ b_in,
                       const float* __restrict__ b_out,
                       __half* __restrict__ binh,
                       __half* __restrict__ bouth)
{
    int idx = blockIdx.x * 256 + threadIdx.x;    // float4 index
    float4 v = reinterpret_cast<const float4*>(b_in)[idx];
    reinterpret_cast<uint2*>(binh)[idx] = f4toh4(v);
    v = reinterpret_cast<const float4*>(b_out)[idx];
    reinterpret_cast<uint2*>(bouth)[idx] = f4toh4(v);
}

// ---------------------------------------------------------------------------
// 1) Embedding gather: Xh[n=b*T+t] = fp16(emb[src[t,b]])
// ---------------------------------------------------------------------------
__global__ void embed_k(const int* __restrict__ src,
                        const float* __restrict__ emb,
                        __half* __restrict__ Xh)
{
    int grp = threadIdx.x >> 6;
    int n   = blockIdx.x * 4 + grp;
    int lu  = threadIdx.x & 63;
    int b = n / T_DIM, t = n % T_DIM;
    int tok = src[t * B_DIM + b];
    float4 v = reinterpret_cast<const float4*>(emb)[(size_t)tok * U4 + lu];
    reinterpret_cast<uint2*>(Xh)[(size_t)n * U4 + lu] = f4toh4(v);
}

// ---------------------------------------------------------------------------
// 2) Fused FP16 GEMM + gates. 1D grid of 960 blocks, 256 threads (8 warps).
//      bid in [0,768): GEMM. 128x128 block tile, 8 warps of 64x32,
//                      BK=64 halves (NT=4), 3-stage cp.async, one barrier
//                      per tile, ldmatrix x4, fp32 accum, fp16 C out.
//      bid in [768,960): gate GEMVs on fp16 X, grid-stride (192 blocks).
// ---------------------------------------------------------------------------
#define GBM 128
#define GBN 128
#define GBK 64                 // halves per k-tile
#define NT  (U_DIM / GBK)      // 4 k-tiles
#define GTHREADS 256
#define GEMM_BLOCKS 768
#define GATE_BLOCKS 192
#define TOTAL_BLOCKS (GEMM_BLOCKS + GATE_BLOCKS)   // 960
#define HPITCH 72              // halves per smem row (144B; ldmatrix conflict-free)
#define A_STAGE_H (GBM * HPITCH)     // 9216 halves
#define B_STAGE_H (GBN * HPITCH)     // 9216 halves
#define SMEM_DYN  (3 * (A_STAGE_H + B_STAGE_H) * 2)   // 110,592 B

__global__ __launch_bounds__(GTHREADS, 2)
void gemm_gate_k(const __half* __restrict__ Ah,
                 const __half* __restrict__ Wh,   // [3][N][K] this layer
                 __half* __restrict__ C0, __half* __restrict__ C1,
                 __half* __restrict__ C2,
                 const float* __restrict__ vgin,
                 const float* __restrict__ vgout,
                 const float* __restrict__ wgl,
                 float* __restrict__ gin, float* __restrict__ gout,
                 float* __restrict__ gloop)
{
    const int bid = blockIdx.x;

    // ---------------- gate slice (grid-stride, fp16 X) ----------------
    if (bid >= GEMM_BLOCKS) {
        int gblk = bid - GEMM_BLOCKS;
        int warp = threadIdx.x >> 5;            // 0..7
        int lane = threadIdx.x & 31;
        const float4* v0 = reinterpret_cast<const float4*>(vgin);
        const float4* v1 = reinterpret_cast<const float4*>(vgout);
        const float4* v2 = reinterpret_cast<const float4*>(wgl);
        const int stride = GATE_BLOCKS * 8;     // 1536 warps
#pragma unroll 1
        for (int n = gblk * 8 + warp; n < BT; n += stride) {
            uint4 xu = reinterpret_cast<const uint4*>(
                Ah + (size_t)n * U_DIM)[lane];
            float x[8];
            h8tof8(xu, x);
            float s0 = 0.f, s1 = 0.f, s2 = 0.f;
            int base = lane * 2;    // float4 index into gate vectors
#pragma unroll
            for (int q = 0; q < 2; q++) {
                float4 a = v0[base + q], b = v1[base + q], c = v2[base + q];
                float* xx = x + q * 4;
                s0 += xx[0] * a.x + xx[1] * a.y + xx[2] * a.z + xx[3] * a.w;
                s1 += xx[0] * b.x + xx[1] * b.y + xx[2] * b.z + xx[3] * b.w;
                s2 += xx[0] * c.x + xx[1] * c.y + xx[2] * c.z + xx[3] * c.w;
            }
#pragma unroll
            for (int off = 16; off > 0; off >>= 1) {
                s0 += __shfl_down_sync(0xffffffffu, s0, off);
                s1 += __shfl_down_sync(0xffffffffu, s1, off);
                s2 += __shfl_down_sync(0xffffffffu, s2, off);
            }
            if (lane == 0) { gin[n] = s0; gout[n] = s1; gloop[n] = s2; }
        }
        return;
    }

    // ---------------- GEMM slice ----------------
    const int xb      = bid & 127;
    const int yb      = bid >> 7;              // 0..5
    const int sel     = yb >> 1;
    const int colbase = (yb & 1) * GBN;
    const __half* __restrict__ W = Wh + (size_t)sel * WSZ;   // [N][K]
    __half* __restrict__ C       = (sel == 0) ? C0 : ((sel == 1) ? C1 : C2);
    const int mbase = xb * GBM;

    extern __shared__ __align__(16) __half hsm[];
    __half* Asm = hsm;                         // 3 stages of [GBM][HPITCH]
    __half* Bsm = hsm + 3 * A_STAGE_H;         // 3 stages of [GBN][HPITCH]

    const int tid  = threadIdx.x;
    const int lane = tid & 31;
    const int warp = tid >> 5;                 // 0..7
    const int wm   = (warp & 1) * 64;          // warp M offset (2 warps in M)
    const int wn   = (warp >> 1) * 32;         // warp N offset (4 warps in N)
    const int g    = lane >> 2;                // 0..7
    const int t    = lane & 3;                 // 0..3

    // cp.async: 4x 16B per thread per operand per tile
    // chunk c = tid + j*256: row = c>>3 (0..127), h = (c&7)*8
    const int ldRow = tid >> 3;                // 0..31
    const int ldH   = (tid & 7) * 8;           // 0..56 halves

    const __half* Abase = Ah + (size_t)(mbase + ldRow) * U_DIM + ldH;
    const __half* Wbase = W + (size_t)(colbase + ldRow) * U_DIM + ldH;
    __half* AsmRow = Asm + ldRow * HPITCH + ldH;
    __half* BsmRow = Bsm + ldRow * HPITCH + ldH;

    const uint32_t asmB = (uint32_t)__cvta_generic_to_shared(Asm);
    const uint32_t bsmB = (uint32_t)__cvta_generic_to_shared(Bsm);
    // A x4 fragment base: lane l -> row wm+mi*16+(l&15), k-offset (l>>4)*8
    const uint32_t aOff0 =
        ((wm + (lane & 15)) * HPITCH + ((lane >> 4) << 3)) * 2;
    // B combined x4 (ni pair p): matrices (2p,k0),(2p,k8),(2p+1,k0),(2p+1,k8)
    uint32_t bOff[2];
#pragma unroll
    for (int p = 0; p < 2; p++)
        bOff[p] = ((wn + (2 * p + ((lane >> 4) & 1)) * 8 + (lane & 7)) * HPITCH
                   + (((lane >> 3) & 1) << 3)) * 2;

    float acc[4][4][4];
#pragma unroll
    for (int mi = 0; mi < 4; mi++)
#pragma unroll
        for (int ni = 0; ni < 4; ni++)
#pragma unroll
            for (int c = 0; c < 4; c++) acc[mi][ni][c] = 0.f;

    // prologue: tiles 0 and 1 into stages 0 and 1
#pragma unroll
    for (int j = 0; j < 4; j++) {
        cp16(AsmRow + j * 32 * HPITCH, Abase + (size_t)j * 32 * U_DIM);
        cp16(BsmRow + j * 32 * HPITCH, Wbase + (size_t)j * 32 * U_DIM);
    }
    CP_COMMIT();
#pragma unroll
    for (int j = 0; j < 4; j++) {
        cp16(AsmRow + A_STAGE_H + j * 32 * HPITCH,
             Abase + (size_t)j * 32 * U_DIM + GBK);
        cp16(BsmRow + B_STAGE_H + j * 32 * HPITCH,
             Wbase + (size_t)j * 32 * U_DIM + GBK);
    }
    CP_COMMIT();

#pragma unroll 1
    for (int tile = 0; tile < NT; tile++) {
        if (tile < NT - 1) { CP_WAIT1(); } else { CP_WAIT0(); }
        __syncthreads();   // tile data visible; stage (tile+2)%3 free

        int nxt = tile + 2;
        if (nxt < NT) {
            int s  = nxt % 3;
            int k0 = nxt * GBK;
#pragma unroll
            for (int j = 0; j < 4; j++) {
                cp16(AsmRow + s * A_STAGE_H + j * 32 * HPITCH,
                     Abase + (size_t)j * 32 * U_DIM + k0);
                cp16(BsmRow + s * B_STAGE_H + j * 32 * HPITCH,
                     Wbase + (size_t)j * 32 * U_DIM + k0);
            }
            CP_COMMIT();
        }

        const int st = tile % 3;
        const uint32_t stA = asmB + st * (A_STAGE_H * 2);
        const uint32_t stB = bsmB + st * (B_STAGE_H * 2);
#pragma unroll
        for (int ks = 0; ks < GBK; ks += 16) {
            const uint32_t kByte = ks * 2;
            uint32_t afr[4][4];
#pragma unroll
            for (int mi = 0; mi < 4; mi++)
                LDSM_X4(afr[mi][0], afr[mi][1], afr[mi][2], afr[mi][3],
                        stA + aOff0 + mi * (16 * HPITCH * 2) + kByte);
            uint32_t bfr[4][2];
#pragma unroll
            for (int p = 0; p < 2; p++)
                LDSM_X4(bfr[2 * p][0], bfr[2 * p][1],
                        bfr[2 * p + 1][0], bfr[2 * p + 1][1],
                        stB + bOff[p] + kByte);
#pragma unroll
            for (int mi = 0; mi < 4; mi++)
#pragma unroll
                for (int ni = 0; ni < 4; ni++)
                    mma_f16(acc[mi][ni], afr[mi], bfr[ni]);
        }
    }

    // epilogue: fp16 stores
#pragma unroll
    for (int mi = 0; mi < 4; mi++) {
#pragma unroll
        for (int ni = 0; ni < 4; ni++) {
            int row = mbase + wm + mi * 16 + g;
            int col = colbase + wn + ni * 8 + 2 * t;
            __half2 h0 = __floats2half2_rn(acc[mi][ni][0], acc[mi][ni][1]);
            __half2 h1 = __floats2half2_rn(acc[mi][ni][2], acc[mi][ni][3]);
            *reinterpret_cast<__half2*>(&C[(size_t)row * U_DIM + col])       = h0;
            *reinterpret_cast<__half2*>(&C[(size_t)(row + 8) * U_DIM + col]) = h1;
        }
    }
}

// ---------------------------------------------------------------------------
// 3) Edge aggregation: 32 threads/node, 8 nodes/block; uint4 fp16 gathers,
//    fp16 biases, fp32 accumulation.
// ---------------------------------------------------------------------------
__global__ __launch_bounds__(256)
void agg_k(const __half* __restrict__ XVin,
           const __half* __restrict__ XVout,
           const __half* __restrict__ XVloop,
           const float* __restrict__ gin,
           const float* __restrict__ gout,
           const float* __restrict__ gloop,
           const int* __restrict__ arc_in,
           const int* __restrict__ arc_out,
           const int* __restrict__ lab_in,
           const int* __restrict__ lab_out,
           const __half* __restrict__ binh,
           const float* __restrict__ bg_in,
           const __half* __restrict__ bouth,
           const float* __restrict__ bg_out,
           const float* __restrict__ mask_in,
           const float* __restrict__ mask_out,
           const float* __restrict__ mask_loop,
           const float* __restrict__ sent_mask,
           float* __restrict__ Y, __half* __restrict__ Yh)
{
    int grp = threadIdx.x >> 5;      // node within block (0..7)
    int n   = blockIdx.x * 8 + grp;
    int lu  = threadIdx.x & 31;      // uint4 lane over U

    __shared__ float p_in[8][DEG], p_out[8][DEG], p_loop[8];
    __shared__ int   s_in[8][DEG], s_out[8][DEG], l_in[8][DEG], l_out[8][DEG];

    if (lu < DEG) {
        int d = lu, e = n * DEG + d;
        int si = arc_in[e] * T_DIM + arc_in[E_EDGES + e];
        int li = lab_in[e];
        float gi = gin[si] + bg_in[li];
        p_in[grp][d] = (1.f / (1.f + __expf(-gi))) * mask_in[n * DEG + d];
        s_in[grp][d] = si; l_in[grp][d] = li;
    } else if (lu < 2 * DEG) {
        int d = lu - DEG, e = n * DEG + d;
        int so = arc_out[e] * T_DIM + arc_out[E_EDGES + e];
        int lo = lab_out[e];
        float go = gout[so] + bg_out[lo];
        p_out[grp][d] = (1.f / (1.f + __expf(-go))) * mask_out[n * DEG + d];
        s_out[grp][d] = so; l_out[grp][d] = lo;
    } else if (lu == 2 * DEG) {
        p_loop[grp] = (1.f / (1.f + __expf(-gloop[n]))) * mask_loop[n];
    }
    __syncthreads();

    const uint4* XVin4   = reinterpret_cast<const uint4*>(XVin);
    const uint4* XVout4  = reinterpret_cast<const uint4*>(XVout);
    const uint4* XVloop4 = reinterpret_cast<const uint4*>(XVloop);
    const uint4* bin4    = reinterpret_cast<const uint4*>(binh);
    const uint4* bout4   = reinterpret_cast<const uint4*>(bouth);

    float acc[8], v[8], bb[8];
    {
        float pl = p_loop[grp];
        h8tof8(XVloop4[(size_t)n * U8 + lu], v);
#pragma unroll
        for (int q = 0; q < 8; q++) acc[q] = pl * v[q];
    }

#pragma unroll
    for (int d = 0; d < DEG; d++) {
        float p = p_in[grp][d];
        h8tof8(XVin4[(size_t)s_in[grp][d] * U8 + lu], v);
        h8tof8(bin4[(size_t)l_in[grp][d] * U8 + lu], bb);
#pragma unroll
        for (int q = 0; q < 8; q++)
            acc[q] = fmaf(p, v[q] + bb[q], acc[q]);
        p = p_out[grp][d];
        h8tof8(XVout4[(size_t)s_out[grp][d] * U8 + lu], v);
        h8tof8(bout4[(size_t)l_out[grp][d] * U8 + lu], bb);
#pragma unroll
        for (int q = 0; q < 8; q++)
            acc[q] = fmaf(p, v[q] + bb[q], acc[q]);
    }
    int b = n / T_DIM, t = n % T_DIM;
    float sm = sent_mask[t * B_DIM + b];
#pragma unroll
    for (int q = 0; q < 8; q++)
        acc[q] = fmaxf(acc[q], 0.f) * sm;

    if (Y) {   // fp32 [t,b,u] membank output
        size_t base = ((size_t)t * B_DIM + b) * U4 + lu * 2;
        reinterpret_cast<float4*>(Y)[base] =
            make_float4(acc[0], acc[1], acc[2], acc[3]);
        reinterpret_cast<float4*>(Y)[base + 1] =
            make_float4(acc[4], acc[5], acc[6], acc[7]);
    }
    if (Yh) {  // fp16 node-major (next layer X)
        uint4 u;
        __half2 h;
        h = __floats2half2_rn(acc[0], acc[1]); u.x = *reinterpret_cast<uint32_t*>(&h);
        h = __floats2half2_rn(acc[2], acc[3]); u.y = *reinterpret_cast<uint32_t*>(&h);
        h = __floats2half2_rn(acc[4], acc[5]); u.z = *reinterpret_cast<uint32_t*>(&h);
        h = __floats2half2_rn(acc[6], acc[7]); u.w = *reinterpret_cast<uint32_t*>(&h);
        reinterpret_cast<uint4*>(Yh)[(size_t)n * U8 + lu] = u;
    }
}

// ---------------------------------------------------------------------------
// 4) enc[b] from membank layout
// ---------------------------------------------------------------------------
__global__ void enc_k(const float* __restrict__ MB,
                      const float* __restrict__ sent_mask,
                      float* __restrict__ enc)
{
    int b = blockIdx.x;
    int u = threadIdx.x;  // 0..63
    const float4* M4 = reinterpret_cast<const float4*>(MB);
    float4 s = make_float4(0.f, 0.f, 0.f, 0.f);
#pragma unroll 4
    for (int t = 0; t < T_DIM; t++) {
        float4 v = M4[((size_t)t * B_DIM + b) * U4 + u];
        s.x += v.x; s.y += v.y; s.z += v.z; s.w += v.w;
    }
    __shared__ float ms;
    if (u == 0) {
        float m = 0.f;
        for (int t = 0; t < T_DIM; t++) m += sent_mask[t * B_DIM + b];
        ms = m;
    }
    __syncthreads();
    float inv = 1.f / ms;
    s.x *= inv; s.y *= inv; s.z *= inv; s.w *= inv;
    reinterpret_cast<float4*>(enc)[b * U4 + u] = s;
}

// ---------------------------------------------------------------------------
// 5) h_all[k,b,w] = sum_u enc[b,u] * H[k,u,w]
// ---------------------------------------------------------------------------
__global__ void hall_k(const float* __restrict__ enc,
                       const float* __restrict__ H,
                       float* __restrict__ out)
{
    int k = blockIdx.y, b = blockIdx.x, w = threadIdx.x;
    __shared__ float es[U_DIM];
    es[w] = enc[b * U_DIM + w];
    __syncthreads();
    const float* Hk = H + (size_t)k * U_DIM * U_DIM;
    float acc = 0.f;
#pragma unroll 8
    for (int u = 0; u < U_DIM; u++)
        acc = fmaf(es[u], Hk[u * U_DIM + w], acc);
    out[((size_t)k * B_DIM + b) * U_DIM + w] = acc;
}

// ---------------------------------------------------------------------------
// Launch
// ---------------------------------------------------------------------------
extern "C" void kernel_launch(void* const* d_in, const int* in_sizes, int n_in,
                              void* d_out, int out_size)
{
    const int*   src       = (const int*)  d_in[0];
    const int*   arc_in    = (const int*)  d_in[1];
    const int*   arc_out   = (const int*)  d_in[2];
    const int*   lab_in    = (const int*)  d_in[3];
    const int*   lab_out   = (const int*)  d_in[4];
    const float* mask_in   = (const float*)d_in[5];
    const float* mask_out  = (const float*)d_in[6];
    const float* mask_loop = (const float*)d_in[7];
    const float* sent_mask = (const float*)d_in[8];
    const float* emb       = (const float*)d_in[9];
    const float* V_in      = (const float*)d_in[10];
    const float* b_in      = (const float*)d_in[11];
    const float* Vg_in     = (const float*)d_in[12];
    const float* bg_in     = (const float*)d_in[13];
    const float* V_out     = (const float*)d_in[14];
    const float* b_out     = (const float*)d_in[15];
    const float* Vg_out    = (const float*)d_in[16];
    const float* bg_out    = (const float*)d_in[17];
    const float* W_loop    = (const float*)d_in[18];
    const float* Wg_loop   = (const float*)d_in[19];
    const float* H         = (const float*)d_in[20];
    float* out = (float*)d_out;

    float *pgin, *pgout, *pgloop, *penc;
    __half *pXh, *pWh, *pbinh, *pbouth, *pXVin, *pXVout, *pXVloop;
    cudaGetSymbolAddress((void**)&pXh,     g_Xh);
    cudaGetSymbolAddress((void**)&pWh,     g_Wh);
    cudaGetSymbolAddress((void**)&pbinh,   g_binh);
    cudaGetSymbolAddress((void**)&pbouth,  g_bouth);
    cudaGetSymbolAddress((void**)&pXVin,   g_XVin);
    cudaGetSymbolAddress((void**)&pXVout,  g_XVout);
    cudaGetSymbolAddress((void**)&pXVloop, g_XVloop);
    cudaGetSymbolAddress((void**)&pgin,    g_gin);
    cudaGetSymbolAddress((void**)&pgout,   g_gout);
    cudaGetSymbolAddress((void**)&pgloop,  g_gloop);
    cudaGetSymbolAddress((void**)&penc,    g_enc);

    cudaFuncSetAttribute(gemm_gate_k,
                         cudaFuncAttributeMaxDynamicSharedMemorySize, SMEM_DYN);

    float* memOut = out + 4 * B_DIM * U_DIM;   // membank region of d_out

    cvtwT_k<<<dim3(8, 8, 6), dim3(32, 32)>>>(V_in, V_out, W_loop, pWh);
    cvtb_k<<<L_LAYERS * NL_LAB * U_DIM / 4 / 256, 256>>>(b_in, b_out,
                                                         pbinh, pbouth);
    embed_k<<<BT / 4, 256>>>(src, emb, pXh);

    for (int l = 0; l < L_LAYERS; l++) {
        const size_t gOff  = (size_t)l * U_DIM;
        const size_t bOff  = (size_t)l * NL_LAB * U_DIM;
        const size_t bgOff = (size_t)l * NL_LAB;
        const int last = (l == L_LAYERS - 1);

        gemm_gate_k<<<TOTAL_BLOCKS, GTHREADS, SMEM_DYN>>>(
            pXh, pWh + (size_t)l * 3 * WSZ,
            pXVin, pXVout, pXVloop,
            Vg_in + gOff, Vg_out + gOff, Wg_loop + gOff,
            pgin, pgout, pgloop);
        agg_k<<<BT / 8, 256>>>(pXVin, pXVout, pXVloop, pgin, pgout, pgloop,
                               arc_in, arc_out, lab_in, lab_out,
                               pbinh + bOff, bg_in + bgOff,
                               pbouth + bOff, bg_out + bgOff,
                               mask_in, mask_out, mask_loop, sent_mask,
                               last ? memOut : nullptr,
                               last ? nullptr : pXh);
    }

    enc_k<<<B_DIM, 64>>>(memOut, sent_mask, penc);
    hall_k<<<dim3(B_DIM, 4), U_DIM>>>(penc, H, out);
}

// round 17
// speedup vs baseline: 1.1259x; 1.0827x over previous
#include <cuda_runtime.h>
#include <cuda_fp16.h>
#include <cstdint>

// Problem constants
#define L_LAYERS 2
#define U_DIM    256
#define U4       (U_DIM / 4)
#define U8       (U_DIM / 8)
#define NL_LAB   64
#define B_DIM    128
#define T_DIM    128
#define DEG      5
#define BT       (B_DIM * T_DIM)          // 16384 nodes
#define E_EDGES  (BT * DEG)               // 81920
#define WSZ      (U_DIM * U_DIM)          // 65536 elems per weight matrix

// ---------------------------------------------------------------------------
// Scratch (device globals — no allocation allowed)
// ---------------------------------------------------------------------------
__device__ __half g_Xh[BT * U_DIM];               // fp16 X (GEMM A + gates)
__device__ __half g_Wh[L_LAYERS * 3 * WSZ];       // fp16 W^T, [l][sel][N][K]
__device__ __half g_binh[L_LAYERS * NL_LAB * U_DIM];   // fp16 label biases
__device__ __half g_bouth[L_LAYERS * NL_LAB * U_DIM];
__device__ __half g_XVin[BT * U_DIM];             // fp16 GEMM outputs
__device__ __half g_XVout[BT * U_DIM];
__device__ __half g_XVloop[BT * U_DIM];
__device__ float  g_gin[BT];
__device__ float  g_gout[BT];
__device__ float  g_gloop[BT];
__device__ float  g_enc[B_DIM * U_DIM];

// ---------------------------------------------------------------------------
// helpers
// ---------------------------------------------------------------------------
__device__ __forceinline__ uint2 f4toh4(float4 v) {
    __half2 h01 = __floats2half2_rn(v.x, v.y);
    __half2 h23 = __floats2half2_rn(v.z, v.w);
    uint2 r;
    r.x = *reinterpret_cast<uint32_t*>(&h01);
    r.y = *reinterpret_cast<uint32_t*>(&h23);
    return r;
}

__device__ __forceinline__ void h8tof8(uint4 u, float* f) {
    float2 p;
    p = __half22float2(*reinterpret_cast<__half2*>(&u.x)); f[0] = p.x; f[1] = p.y;
    p = __half22float2(*reinterpret_cast<__half2*>(&u.y)); f[2] = p.x; f[3] = p.y;
    p = __half22float2(*reinterpret_cast<__half2*>(&u.z)); f[4] = p.x; f[5] = p.y;
    p = __half22float2(*reinterpret_cast<__half2*>(&u.w)); f[6] = p.x; f[7] = p.y;
}

__device__ __forceinline__ void mma_f16(float* d, const uint32_t* a,
                                        const uint32_t* b) {
    asm volatile(
        "mma.sync.aligned.m16n8k16.row.col.f32.f16.f16.f32 "
        "{%0,%1,%2,%3}, {%4,%5,%6,%7}, {%8,%9}, {%0,%1,%2,%3};\n"
        : "+f"(d[0]), "+f"(d[1]), "+f"(d[2]), "+f"(d[3])
        : "r"(a[0]), "r"(a[1]), "r"(a[2]), "r"(a[3]), "r"(b[0]), "r"(b[1]));
}

#define LDSM_X4(r0, r1, r2, r3, addr) \
    asm volatile("ldmatrix.sync.aligned.m8n8.x4.shared.b16 {%0,%1,%2,%3}, [%4];" \
                 : "=r"(r0), "=r"(r1), "=r"(r2), "=r"(r3) : "r"(addr))

__device__ __forceinline__ void cp16(void* dst, const void* src) {
    uint32_t d = (uint32_t)__cvta_generic_to_shared(dst);
    asm volatile("cp.async.cg.shared.global [%0], [%1], 16;\n"
                 :: "r"(d), "l"(src));
}
#define CP_COMMIT() asm volatile("cp.async.commit_group;\n" ::: "memory")
#define CP_WAIT1()  asm volatile("cp.async.wait_group 1;\n" ::: "memory")
#define CP_WAIT0()  asm volatile("cp.async.wait_group 0;\n" ::: "memory")

// ---------------------------------------------------------------------------
// 0a) Weight convert + transpose: Wh[l][sel][n][k] = fp16(W[l][sel][k][n])
// ---------------------------------------------------------------------------
__global__ void cvtwT_k(const float* __restrict__ Vin,
                        const float* __restrict__ Vout,
                        const float* __restrict__ Wloop,
                        __half* __restrict__ out)
{
    __shared__ float ts[32][33];
    int z = blockIdx.z;                  // l*3 + sel
    int l = z / 3, sel = z % 3;
    const float* src = ((sel == 0) ? Vin : (sel == 1) ? Vout : Wloop)
                       + (size_t)l * WSZ;
    __half* dst = out + (size_t)z * WSZ;
    int kk = blockIdx.y * 32 + threadIdx.y;
    int nn = blockIdx.x * 32 + threadIdx.x;
    ts[threadIdx.y][threadIdx.x] = src[(size_t)kk * U_DIM + nn];
    __syncthreads();
    int on = blockIdx.x * 32 + threadIdx.y;
    int ok = blockIdx.y * 32 + threadIdx.x;
    dst[(size_t)on * U_DIM + ok] = __float2half_rn(ts[threadIdx.x][threadIdx.y]);
}

// ---------------------------------------------------------------------------
// 0b) Bias convert: fp32 [L*NL*U] -> fp16, both in and out tables.
// ---------------------------------------------------------------------------
__global__ void cvtb_k(const float* __restrict__ b_in,
                       const float* __restrict__ b_out,
                       __half* __restrict__ binh,
                       __half* __restrict__ bouth)
{
    int idx = blockIdx.x * 256 + threadIdx.x;    // float4 index
    float4 v = reinterpret_cast<const float4*>(b_in)[idx];
    reinterpret_cast<uint2*>(binh)[idx] = f4toh4(v);
    v = reinterpret_cast<const float4*>(b_out)[idx];
    reinterpret_cast<uint2*>(bouth)[idx] = f4toh4(v);
}

// ---------------------------------------------------------------------------
// 1) Embedding gather: Xh[n=b*T+t] = fp16(emb[src[t,b]])
// ---------------------------------------------------------------------------
__global__ void embed_k(const int* __restrict__ src,
                        const float* __restrict__ emb,
                        __half* __restrict__ Xh)
{
    int grp = threadIdx.x >> 6;
    int n   = blockIdx.x * 4 + grp;
    int lu  = threadIdx.x & 63;
    int b = n / T_DIM, t = n % T_DIM;
    int tok = src[t * B_DIM + b];
    float4 v = reinterpret_cast<const float4*>(emb)[(size_t)tok * U4 + lu];
    reinterpret_cast<uint2*>(Xh)[(size_t)n * U4 + lu] = f4toh4(v);
}

// ---------------------------------------------------------------------------
// 2) Fused FP16 GEMM + gates. 1D grid of 888 blocks (= 3 exact waves at
//    2 CTAs/SM x 148 SMs), 256 threads (8 warps).
//      bid in [0,768): GEMM. 128x128 block tile, 8 warps of 64x32,
//                      BK=64 halves (NT=4), 3-stage cp.async, one barrier
//                      per tile, ldmatrix x4, fp32 accum, fp16 C out.
//      bid in [768,888): gate GEMVs on fp16 X, grid-stride (120 blocks).
// ---------------------------------------------------------------------------
#define GBM 128
#define GBN 128
#define GBK 64                 // halves per k-tile
#define NT  (U_DIM / GBK)      // 4 k-tiles
#define GTHREADS 256
#define GEMM_BLOCKS 768
#define GATE_BLOCKS 120
#define TOTAL_BLOCKS (GEMM_BLOCKS + GATE_BLOCKS)   // 888 = 296*3
#define HPITCH 72              // halves per smem row (144B; ldmatrix conflict-free)
#define A_STAGE_H (GBM * HPITCH)     // 9216 halves
#define B_STAGE_H (GBN * HPITCH)     // 9216 halves
#define SMEM_DYN  (3 * (A_STAGE_H + B_STAGE_H) * 2)   // 110,592 B

__global__ __launch_bounds__(GTHREADS, 2)
void gemm_gate_k(const __half* __restrict__ Ah,
                 const __half* __restrict__ Wh,   // [3][N][K] this layer
                 __half* __restrict__ C0, __half* __restrict__ C1,
                 __half* __restrict__ C2,
                 const float* __restrict__ vgin,
                 const float* __restrict__ vgout,
                 const float* __restrict__ wgl,
                 float* __restrict__ gin, float* __restrict__ gout,
                 float* __restrict__ gloop)
{
    const int bid = blockIdx.x;

    // ---------------- gate slice (grid-stride, fp16 X) ----------------
    if (bid >= GEMM_BLOCKS) {
        int gblk = bid - GEMM_BLOCKS;
        int warp = threadIdx.x >> 5;            // 0..7
        int lane = threadIdx.x & 31;
        const float4* v0 = reinterpret_cast<const float4*>(vgin);
        const float4* v1 = reinterpret_cast<const float4*>(vgout);
        const float4* v2 = reinterpret_cast<const float4*>(wgl);
        const int stride = GATE_BLOCKS * 8;     // 960 warps
#pragma unroll 1
        for (int n = gblk * 8 + warp; n < BT; n += stride) {
            uint4 xu = reinterpret_cast<const uint4*>(
                Ah + (size_t)n * U_DIM)[lane];
            float x[8];
            h8tof8(xu, x);
            float s0 = 0.f, s1 = 0.f, s2 = 0.f;
            int base = lane * 2;    // float4 index into gate vectors
#pragma unroll
            for (int q = 0; q < 2; q++) {
                float4 a = v0[base + q], b = v1[base + q], c = v2[base + q];
                float* xx = x + q * 4;
                s0 += xx[0] * a.x + xx[1] * a.y + xx[2] * a.z + xx[3] * a.w;
                s1 += xx[0] * b.x + xx[1] * b.y + xx[2] * b.z + xx[3] * b.w;
                s2 += xx[0] * c.x + xx[1] * c.y + xx[2] * c.z + xx[3] * c.w;
            }
#pragma unroll
            for (int off = 16; off > 0; off >>= 1) {
                s0 += __shfl_down_sync(0xffffffffu, s0, off);
                s1 += __shfl_down_sync(0xffffffffu, s1, off);
                s2 += __shfl_down_sync(0xffffffffu, s2, off);
            }
            if (lane == 0) { gin[n] = s0; gout[n] = s1; gloop[n] = s2; }
        }
        return;
    }

    // ---------------- GEMM slice ----------------
    const int xb      = bid & 127;
    const int yb      = bid >> 7;              // 0..5
    const int sel     = yb >> 1;
    const int colbase = (yb & 1) * GBN;
    const __half* __restrict__ W = Wh + (size_t)sel * WSZ;   // [N][K]
    __half* __restrict__ C       = (sel == 0) ? C0 : ((sel == 1) ? C1 : C2);
    const int mbase = xb * GBM;

    extern __shared__ __align__(16) __half hsm[];
    __half* Asm = hsm;                         // 3 stages of [GBM][HPITCH]
    __half* Bsm = hsm + 3 * A_STAGE_H;         // 3 stages of [GBN][HPITCH]

    const int tid  = threadIdx.x;
    const int lane = tid & 31;
    const int warp = tid >> 5;                 // 0..7
    const int wm   = (warp & 1) * 64;          // warp M offset (2 warps in M)
    const int wn   = (warp >> 1) * 32;         // warp N offset (4 warps in N)
    const int g    = lane >> 2;                // 0..7
    const int t    = lane & 3;                 // 0..3

    // cp.async: 4x 16B per thread per operand per tile
    const int ldRow = tid >> 3;                // 0..31
    const int ldH   = (tid & 7) * 8;           // 0..56 halves

    const __half* Abase = Ah + (size_t)(mbase + ldRow) * U_DIM + ldH;
    const __half* Wbase = W + (size_t)(colbase + ldRow) * U_DIM + ldH;
    __half* AsmRow = Asm + ldRow * HPITCH + ldH;
    __half* BsmRow = Bsm + ldRow * HPITCH + ldH;

    const uint32_t asmB = (uint32_t)__cvta_generic_to_shared(Asm);
    const uint32_t bsmB = (uint32_t)__cvta_generic_to_shared(Bsm);
    // A x4 fragment base: lane l -> row wm+mi*16+(l&15), k-offset (l>>4)*8
    const uint32_t aOff0 =
        ((wm + (lane & 15)) * HPITCH + ((lane >> 4) << 3)) * 2;
    // B combined x4 (ni pair p): matrices (2p,k0),(2p,k8),(2p+1,k0),(2p+1,k8)
    uint32_t bOff[2];
#pragma unroll
    for (int p = 0; p < 2; p++)
        bOff[p] = ((wn + (2 * p + ((lane >> 4) & 1)) * 8 + (lane & 7)) * HPITCH
                   + (((lane >> 3) & 1) << 3)) * 2;

    float acc[4][4][4];
#pragma unroll
    for (int mi = 0; mi < 4; mi++)
#pragma unroll
        for (int ni = 0; ni < 4; ni++)
#pragma unroll
            for (int c = 0; c < 4; c++) acc[mi][ni][c] = 0.f;

    // prologue: tiles 0 and 1 into stages 0 and 1
#pragma unroll
    for (int j = 0; j < 4; j++) {
        cp16(AsmRow + j * 32 * HPITCH, Abase + (size_t)j * 32 * U_DIM);
        cp16(BsmRow + j * 32 * HPITCH, Wbase + (size_t)j * 32 * U_DIM);
    }
    CP_COMMIT();
#pragma unroll
    for (int j = 0; j < 4; j++) {
        cp16(AsmRow + A_STAGE_H + j * 32 * HPITCH,
             Abase + (size_t)j * 32 * U_DIM + GBK);
        cp16(BsmRow + B_STAGE_H + j * 32 * HPITCH,
             Wbase + (size_t)j * 32 * U_DIM + GBK);
    }
    CP_COMMIT();

#pragma unroll 1
    for (int tile = 0; tile < NT; tile++) {
        if (tile < NT - 1) { CP_WAIT1(); } else { CP_WAIT0(); }
        __syncthreads();   // tile data visible; stage (tile+2)%3 free

        int nxt = tile + 2;
        if (nxt < NT) {
            int s  = nxt % 3;
            int k0 = nxt * GBK;
#pragma unroll
            for (int j = 0; j < 4; j++) {
                cp16(AsmRow + s * A_STAGE_H + j * 32 * HPITCH,
                     Abase + (size_t)j * 32 * U_DIM + k0);
                cp16(BsmRow + s * B_STAGE_H + j * 32 * HPITCH,
                     Wbase + (size_t)j * 32 * U_DIM + k0);
            }
            CP_COMMIT();
        }

        const int st = tile % 3;
        const uint32_t stA = asmB + st * (A_STAGE_H * 2);
        const uint32_t stB = bsmB + st * (B_STAGE_H * 2);
#pragma unroll
        for (int ks = 0; ks < GBK; ks += 16) {
            const uint32_t kByte = ks * 2;
            uint32_t afr[4][4];
#pragma unroll
            for (int mi = 0; mi < 4; mi++)
                LDSM_X4(afr[mi][0], afr[mi][1], afr[mi][2], afr[mi][3],
                        stA + aOff0 + mi * (16 * HPITCH * 2) + kByte);
            uint32_t bfr[4][2];
#pragma unroll
            for (int p = 0; p < 2; p++)
                LDSM_X4(bfr[2 * p][0], bfr[2 * p][1],
                        bfr[2 * p + 1][0], bfr[2 * p + 1][1],
                        stB + bOff[p] + kByte);
#pragma unroll
            for (int mi = 0; mi < 4; mi++)
#pragma unroll
                for (int ni = 0; ni < 4; ni++)
                    mma_f16(acc[mi][ni], afr[mi], bfr[ni]);
        }
    }

    // epilogue: fp16 stores
#pragma unroll
    for (int mi = 0; mi < 4; mi++) {
#pragma unroll
        for (int ni = 0; ni < 4; ni++) {
            int row = mbase + wm + mi * 16 + g;
            int col = colbase + wn + ni * 8 + 2 * t;
            __half2 h0 = __floats2half2_rn(acc[mi][ni][0], acc[mi][ni][1]);
            __half2 h1 = __floats2half2_rn(acc[mi][ni][2], acc[mi][ni][3]);
            *reinterpret_cast<__half2*>(&C[(size_t)row * U_DIM + col])       = h0;
            *reinterpret_cast<__half2*>(&C[(size_t)(row + 8) * U_DIM + col]) = h1;
        }
    }
}

// ---------------------------------------------------------------------------
// 3) Edge aggregation: 32 threads/node, 8 nodes/block; uint4 fp16 gathers,
//    fp16 biases, fp32 accumulation.
// ---------------------------------------------------------------------------
__global__ __launch_bounds__(256)
void agg_k(const __half* __restrict__ XVin,
           const __half* __restrict__ XVout,
           const __half* __restrict__ XVloop,
           const float* __restrict__ gin,
           const float* __restrict__ gout,
           const float* __restrict__ gloop,
           const int* __restrict__ arc_in,
           const int* __restrict__ arc_out,
           const int* __restrict__ lab_in,
           const int* __restrict__ lab_out,
           const __half* __restrict__ binh,
           const float* __restrict__ bg_in,
           const __half* __restrict__ bouth,
           const float* __restrict__ bg_out,
           const float* __restrict__ mask_in,
           const float* __restrict__ mask_out,
           const float* __restrict__ mask_loop,
           const float* __restrict__ sent_mask,
           float* __restrict__ Y, __half* __restrict__ Yh)
{
    int grp = threadIdx.x >> 5;      // node within block (0..7)
    int n   = blockIdx.x * 8 + grp;
    int lu  = threadIdx.x & 31;      // uint4 lane over U

    __shared__ float p_in[8][DEG], p_out[8][DEG], p_loop[8];
    __shared__ int   s_in[8][DEG], s_out[8][DEG], l_in[8][DEG], l_out[8][DEG];

    if (lu < DEG) {
        int d = lu, e = n * DEG + d;
        int si = arc_in[e] * T_DIM + arc_in[E_EDGES + e];
        int li = lab_in[e];
        float gi = gin[si] + bg_in[li];
        p_in[grp][d] = (1.f / (1.f + __expf(-gi))) * mask_in[n * DEG + d];
        s_in[grp][d] = si; l_in[grp][d] = li;
    } else if (lu < 2 * DEG) {
        int d = lu - DEG, e = n * DEG + d;
        int so = arc_out[e] * T_DIM + arc_out[E_EDGES + e];
        int lo = lab_out[e];
        float go = gout[so] + bg_out[lo];
        p_out[grp][d] = (1.f / (1.f + __expf(-go))) * mask_out[n * DEG + d];
        s_out[grp][d] = so; l_out[grp][d] = lo;
    } else if (lu == 2 * DEG) {
        p_loop[grp] = (1.f / (1.f + __expf(-gloop[n]))) * mask_loop[n];
    }
    __syncthreads();

    const uint4* XVin4   = reinterpret_cast<const uint4*>(XVin);
    const uint4* XVout4  = reinterpret_cast<const uint4*>(XVout);
    const uint4* XVloop4 = reinterpret_cast<const uint4*>(XVloop);
    const uint4* bin4    = reinterpret_cast<const uint4*>(binh);
    const uint4* bout4   = reinterpret_cast<const uint4*>(bouth);

    float acc[8], v[8], bb[8];
    {
        float pl = p_loop[grp];
        h8tof8(XVloop4[(size_t)n * U8 + lu], v);
#pragma unroll
        for (int q = 0; q < 8; q++) acc[q] = pl * v[q];
    }

#pragma unroll
    for (int d = 0; d < DEG; d++) {
        float p = p_in[grp][d];
        h8tof8(XVin4[(size_t)s_in[grp][d] * U8 + lu], v);
        h8tof8(bin4[(size_t)l_in[grp][d] * U8 + lu], bb);
#pragma unroll
        for (int q = 0; q < 8; q++)
            acc[q] = fmaf(p, v[q] + bb[q], acc[q]);
        p = p_out[grp][d];
        h8tof8(XVout4[(size_t)s_out[grp][d] * U8 + lu], v);
        h8tof8(bout4[(size_t)l_out[grp][d] * U8 + lu], bb);
#pragma unroll
        for (int q = 0; q < 8; q++)
            acc[q] = fmaf(p, v[q] + bb[q], acc[q]);
    }
    int b = n / T_DIM, t = n % T_DIM;
    float sm = sent_mask[t * B_DIM + b];
#pragma unroll
    for (int q = 0; q < 8; q++)
        acc[q] = fmaxf(acc[q], 0.f) * sm;

    if (Y) {   // fp32 [t,b,u] membank output
        size_t base = ((size_t)t * B_DIM + b) * U4 + lu * 2;
        reinterpret_cast<float4*>(Y)[base] =
            make_float4(acc[0], acc[1], acc[2], acc[3]);
        reinterpret_cast<float4*>(Y)[base + 1] =
            make_float4(acc[4], acc[5], acc[6], acc[7]);
    }
    if (Yh) {  // fp16 node-major (next layer X)
        uint4 u;
        __half2 h;
        h = __floats2half2_rn(acc[0], acc[1]); u.x = *reinterpret_cast<uint32_t*>(&h);
        h = __floats2half2_rn(acc[2], acc[3]); u.y = *reinterpret_cast<uint32_t*>(&h);
        h = __floats2half2_rn(acc[4], acc[5]); u.z = *reinterpret_cast<uint32_t*>(&h);
        h = __floats2half2_rn(acc[6], acc[7]); u.w = *reinterpret_cast<uint32_t*>(&h);
        reinterpret_cast<uint4*>(Yh)[(size_t)n * U8 + lu] = u;
    }
}

// ---------------------------------------------------------------------------
// 4) enc[b] from membank layout — segmented deterministic reduction.
//    512 threads: 8 t-segments x 64 float4 columns; fixed-order combine.
// ---------------------------------------------------------------------------
__global__ __launch_bounds__(512)
void enc_k(const float* __restrict__ MB,
           const float* __restrict__ sent_mask,
           float* __restrict__ enc)
{
    int b   = blockIdx.x;
    int seg = threadIdx.x >> 6;      // 0..7
    int c   = threadIdx.x & 63;      // float4 column
    __shared__ float4 part[8][64];
    __shared__ float ms;
    const float4* M4 = reinterpret_cast<const float4*>(MB);
    float4 s = make_float4(0.f, 0.f, 0.f, 0.f);
#pragma unroll
    for (int i = 0; i < 16; i++) {
        int t = seg * 16 + i;
        float4 v = M4[((size_t)t * B_DIM + b) * U4 + c];
        s.x += v.x; s.y += v.y; s.z += v.z; s.w += v.w;
    }
    part[seg][c] = s;
    if (threadIdx.x == 0) {
        float m = 0.f;
        for (int t = 0; t < T_DIM; t++) m += sent_mask[t * B_DIM + b];
        ms = m;
    }
    __syncthreads();
    if (seg == 0) {
        float4 r = part[0][c];
#pragma unroll
        for (int k = 1; k < 8; k++) {
            float4 v = part[k][c];
            r.x += v.x; r.y += v.y; r.z += v.z; r.w += v.w;
        }
        float inv = 1.f / ms;
        r.x *= inv; r.y *= inv; r.z *= inv; r.w *= inv;
        reinterpret_cast<float4*>(enc)[b * U4 + c] = r;
    }
}

// ---------------------------------------------------------------------------
// 5) h_all[k,b,w] = sum_u enc[b,u] * H[k,u,w]
// ---------------------------------------------------------------------------
__global__ void hall_k(const float* __restrict__ enc,
                       const float* __restrict__ H,
                       float* __restrict__ out)
{
    int k = blockIdx.y, b = blockIdx.x, w = threadIdx.x;
    __shared__ float es[U_DIM];
    es[w] = enc[b * U_DIM + w];
    __syncthreads();
    const float* Hk = H + (size_t)k * U_DIM * U_DIM;
    float acc = 0.f;
#pragma unroll 8
    for (int u = 0; u < U_DIM; u++)
        acc = fmaf(es[u], Hk[u * U_DIM + w], acc);
    out[((size_t)k * B_DIM + b) * U_DIM + w] = acc;
}

// ---------------------------------------------------------------------------
// Launch
// ---------------------------------------------------------------------------
extern "C" void kernel_launch(void* const* d_in, const int* in_sizes, int n_in,
                              void* d_out, int out_size)
{
    const int*   src       = (const int*)  d_in[0];
    const int*   arc_in    = (const int*)  d_in[1];
    const int*   arc_out   = (const int*)  d_in[2];
    const int*   lab_in    = (const int*)  d_in[3];
    const int*   lab_out   = (const int*)  d_in[4];
    const float* mask_in   = (const float*)d_in[5];
    const float* mask_out  = (const float*)d_in[6];
    const float* mask_loop = (const float*)d_in[7];
    const float* sent_mask = (const float*)d_in[8];
    const float* emb       = (const float*)d_in[9];
    const float* V_in      = (const float*)d_in[10];
    const float* b_in      = (const float*)d_in[11];
    const float* Vg_in     = (const float*)d_in[12];
    const float* bg_in     = (const float*)d_in[13];
    const float* V_out     = (const float*)d_in[14];
    const float* b_out     = (const float*)d_in[15];
    const float* Vg_out    = (const float*)d_in[16];
    const float* bg_out    = (const float*)d_in[17];
    const float* W_loop    = (const float*)d_in[18];
    const float* Wg_loop   = (const float*)d_in[19];
    const float* H         = (const float*)d_in[20];
    float* out = (float*)d_out;

    float *pgin, *pgout, *pgloop, *penc;
    __half *pXh, *pWh, *pbinh, *pbouth, *pXVin, *pXVout, *pXVloop;
    cudaGetSymbolAddress((void**)&pXh,     g_Xh);
    cudaGetSymbolAddress((void**)&pWh,     g_Wh);
    cudaGetSymbolAddress((void**)&pbinh,   g_binh);
    cudaGetSymbolAddress((void**)&pbouth,  g_bouth);
    cudaGetSymbolAddress((void**)&pXVin,   g_XVin);
    cudaGetSymbolAddress((void**)&pXVout,  g_XVout);
    cudaGetSymbolAddress((void**)&pXVloop, g_XVloop);
    cudaGetSymbolAddress((void**)&pgin,    g_gin);
    cudaGetSymbolAddress((void**)&pgout,   g_gout);
    cudaGetSymbolAddress((void**)&pgloop,  g_gloop);
    cudaGetSymbolAddress((void**)&penc,    g_enc);

    cudaFuncSetAttribute(gemm_gate_k,
                         cudaFuncAttributeMaxDynamicSharedMemorySize, SMEM_DYN);

    float* memOut = out + 4 * B_DIM * U_DIM;   // membank region of d_out

    cvtwT_k<<<dim3(8, 8, 6), dim3(32, 32)>>>(V_in, V_out, W_loop, pWh);
    cvtb_k<<<L_LAYERS * NL_LAB * U_DIM / 4 / 256, 256>>>(b_in, b_out,
                                                         pbinh, pbouth);
    embed_k<<<BT / 4, 256>>>(src, emb, pXh);

    for (int l = 0; l < L_LAYERS; l++) {
        const size_t gOff  = (size_t)l * U_DIM;
        const size_t bOff  = (size_t)l * NL_LAB * U_DIM;
        const size_t bgOff = (size_t)l * NL_LAB;
        const int last = (l == L_LAYERS - 1);

        gemm_gate_k<<<TOTAL_BLOCKS, GTHREADS, SMEM_DYN>>>(
            pXh, pWh + (size_t)l * 3 * WSZ,
            pXVin, pXVout, pXVloop,
            Vg_in + gOff, Vg_out + gOff, Wg_loop + gOff,
            pgin, pgout, pgloop);
        agg_k<<<BT / 8, 256>>>(pXVin, pXVout, pXVloop, pgin, pgout, pgloop,
                               arc_in, arc_out, lab_in, lab_out,
                               pbinh + bOff, bg_in + bgOff,
                               pbouth + bOff, bg_out + bgOff,
                               mask_in, mask_out, mask_loop, sent_mask,
                               last ? memOut : nullptr,
                               last ? nullptr : pXh);
    }

    enc_k<<<B_DIM, 512>>>(memOut, sent_mask, penc);
    hall_k<<<dim3(B_DIM, 4), U_DIM>>>(penc, H, out);
}